// round 8
// baseline (speedup 1.0000x reference)
#include <cuda_runtime.h>
#include <cstdint>

// out[(b*64+n), :] = x[(b*64+n), :] @ W[n] / 16
// x: [4096*64, 256] f32, W: [64, 256, 256] f32, out: [4096*64, 256] f32
#define NODES   64
#define FDIM    256
#define ODIM    256
#define NGRAPH  4096

#define BM 128          // graphs per CTA
#define BN 128          // output cols per CTA
#define KC 64           // k-chunk (A staging granularity)
#define NKC (FDIM / KC) // 4
#define A_PAD 68        // floats per A smem row (64 data + 4 pad)
#define NSTAGE 3
#define NTHREADS 128    // 4 warps, each owns a 64x64 warp tile

#define A_STAGE_FLOATS (BM * A_PAD)         // 8704
#define SMEM_BYTES (NSTAGE * A_STAGE_FLOATS * 4)   // 104448

// packed W granularity: per (node, 32-k chunk): 2048 float4 = 32 k x 256 cols
#define CHUNK_F4 2048

__device__ __forceinline__ uint32_t smem_u32(const void* p) {
    return (uint32_t)__cvta_generic_to_shared(p);
}
__device__ __forceinline__ void cp_async16(uint32_t s, const void* g) {
    asm volatile("cp.async.cg.shared.global [%0], [%1], 16;" :: "r"(s), "l"(g));
}

// Packed, pre-scaled, tf32-rounded W fragments (same layout as R5-R7):
// [n][chunk32][wn(0..3)][s(0..3)][j(0..3)][lane(0..31)] as float4:
//   {W'(k0,o0), W'(k0+4,o0), W'(k0,o1), W'(k0+4,o1)}
//   k0 = chunk32*32 + s*8 + tig, o0 = wn*64 + 2*j*8 + gid, o1 = o0 + 8
__device__ float4 Wp_g[NODES * (FDIM / 32) * CHUNK_F4];   // 16 MB (L2-resident)

__global__ void pack_w_kernel(const float* __restrict__ W) {
    __shared__ float sw[32 * ODIM];     // 32 x 256 = 32KB
    const int n = blockIdx.y;
    const int chunk = blockIdx.x;       // 32-k granularity, 0..7
    const int tid = threadIdx.x;
    const float4* src = (const float4*)(W + (size_t)n * FDIM * ODIM + (size_t)chunk * 32 * ODIM);
    float4* dst = (float4*)sw;
    #pragma unroll
    for (int i = 0; i < 8; i++)
        dst[tid + i * 256] = src[tid + i * 256];
    __syncthreads();

    // scale = 1/16 * (1 + 2^-11): compensates HW tf32 truncation bias on x
    const float sc = 0.0625f * 1.00048828125f;
    float4* outp = Wp_g + ((size_t)n * (FDIM / 32) + chunk) * CHUNK_F4;
    #pragma unroll
    for (int i = 0; i < 8; i++) {
        int c = tid + i * 256;          // 0..2047
        int lane = c & 31;
        int j    = (c >> 5) & 3;
        int s    = (c >> 7) & 3;
        int wn   = c >> 9;              // 0..3
        int gid = lane >> 2, tig = lane & 3;
        int k  = s * 8 + tig;
        int o0 = wn * 64 + 2 * j * 8 + gid;
        float4 v;
        uint32_t u;
        float t;
        t = sw[k * ODIM + o0] * sc;
        asm("cvt.rna.tf32.f32 %0, %1;" : "=r"(u) : "f"(t)); v.x = __uint_as_float(u);
        t = sw[(k + 4) * ODIM + o0] * sc;
        asm("cvt.rna.tf32.f32 %0, %1;" : "=r"(u) : "f"(t)); v.y = __uint_as_float(u);
        t = sw[k * ODIM + o0 + 8] * sc;
        asm("cvt.rna.tf32.f32 %0, %1;" : "=r"(u) : "f"(t)); v.z = __uint_as_float(u);
        t = sw[(k + 4) * ODIM + o0 + 8] * sc;
        asm("cvt.rna.tf32.f32 %0, %1;" : "=r"(u) : "f"(t)); v.w = __uint_as_float(u);
        outp[c] = v;
    }
}

__global__ void __launch_bounds__(NTHREADS, 2)
linear_mlp_node_kernel(const float* __restrict__ x, float* __restrict__ out) {
    extern __shared__ float smem[];
    float* sA = smem;                                  // [NSTAGE][BM][A_PAD]

    const int tid   = threadIdx.x;
    const int btile = blockIdx.x;   // 0..31
    const int ntile = blockIdx.y;   // 0..1
    const int n     = blockIdx.z;   // 0..63

    const int warp = tid >> 5;      // 0..3
    const int lane = tid & 31;
    const int wm = warp & 1;        // rows wm*64..+63
    const int wn = warp >> 1;       // cols wn*64..+63 (within this CTA's 128)
    const int gid = lane >> 2;
    const int tig = lane & 3;

    const int wnp = ntile * 2 + wn;                         // packed wn index 0..3
    const float4* __restrict__ WpN = Wp_g + (size_t)n * (FDIM / 32) * CHUNK_F4
                                   + (size_t)wnp * 512 + lane;

    // B fragments for global k-step gs (0..31): direct from L2, coalesced LDG.128
    auto ldB = [&](int gs, float4* bb) {
        const float4* p = WpN + (size_t)(gs >> 2) * CHUNK_F4 + (gs & 3) * 128;
        bb[0] = p[0];
        bb[1] = p[32];
        bb[2] = p[64];
        bb[3] = p[96];
    };

    // A chunk load (cp.async): 128 rows x 64 floats = 2048 float4, 16/thread
    auto load_stageA = [&](int kc) {
        float* dA = sA + (kc % NSTAGE) * A_STAGE_FLOATS;
        const int k0 = kc * KC;
        #pragma unroll
        for (int i = 0; i < 16; i++) {
            int c = tid + i * NTHREADS;
            int row = c >> 4, ch = c & 15;
            const float* g = x + ((size_t)(btile * BM + row) * NODES + n) * FDIM + k0 + ch * 4;
            cp_async16(smem_u32(dA + row * A_PAD + ch * 4), g);
        }
        asm volatile("cp.async.commit_group;" ::: "memory");
    };

    float acc[4][8][4];
    #pragma unroll
    for (int mt = 0; mt < 4; mt++)
        #pragma unroll
        for (int nt = 0; nt < 8; nt++)
            #pragma unroll
            for (int r = 0; r < 4; r++)
                acc[mt][nt][r] = 0.0f;

    load_stageA(0);
    load_stageA(1);

    float4 b[2][4];
    ldB(0, b[0]);

    for (int kc = 0; kc < NKC; kc++) {
        if (kc < NKC - 1)
            asm volatile("cp.async.wait_group 1;" ::: "memory");
        else
            asm volatile("cp.async.wait_group 0;" ::: "memory");
        __syncthreads();
        // stage (kc+2)%3 == stage of (kc-1): fully consumed before the barrier
        if (kc + 2 < NKC)
            load_stageA(kc + 2);

        const float* cA = sA + (kc % NSTAGE) * A_STAGE_FLOATS + (wm * 64) * A_PAD;

        #pragma unroll
        for (int s = 0; s < 8; s++) {
            const int gs = kc * 8 + s;
            const int cur = gs & 1;
            if (gs + 1 < 32)
                ldB(gs + 1, b[cur ^ 1]);    // overlaps with MMAs below

            uint32_t a[4][4];
            #pragma unroll
            for (int mt = 0; mt < 4; mt++) {
                const float* p = cA + (mt * 16 + gid) * A_PAD + s * 8 + tig;
                a[mt][0] = __float_as_uint(p[0]);
                a[mt][1] = __float_as_uint(p[8 * A_PAD]);
                a[mt][2] = __float_as_uint(p[4]);
                a[mt][3] = __float_as_uint(p[8 * A_PAD + 4]);
            }
            #pragma unroll
            for (int mt = 0; mt < 4; mt++) {
                #pragma unroll
                for (int j = 0; j < 4; j++) {
                    asm volatile(
                        "mma.sync.aligned.m16n8k8.row.col.f32.tf32.tf32.f32 "
                        "{%0,%1,%2,%3}, {%4,%5,%6,%7}, {%8,%9}, {%0,%1,%2,%3};"
                        : "+f"(acc[mt][2 * j][0]), "+f"(acc[mt][2 * j][1]),
                          "+f"(acc[mt][2 * j][2]), "+f"(acc[mt][2 * j][3])
                        : "r"(a[mt][0]), "r"(a[mt][1]), "r"(a[mt][2]), "r"(a[mt][3]),
                          "r"(__float_as_uint(b[cur][j].x)), "r"(__float_as_uint(b[cur][j].y)));
                    asm volatile(
                        "mma.sync.aligned.m16n8k8.row.col.f32.tf32.tf32.f32 "
                        "{%0,%1,%2,%3}, {%4,%5,%6,%7}, {%8,%9}, {%0,%1,%2,%3};"
                        : "+f"(acc[mt][2 * j + 1][0]), "+f"(acc[mt][2 * j + 1][1]),
                          "+f"(acc[mt][2 * j + 1][2]), "+f"(acc[mt][2 * j + 1][3])
                        : "r"(a[mt][0]), "r"(a[mt][1]), "r"(a[mt][2]), "r"(a[mt][3]),
                          "r"(__float_as_uint(b[cur][j].z)), "r"(__float_as_uint(b[cur][j].w)));
                }
            }
        }
    }

    // epilogue (scale already folded into W)
    #pragma unroll
    for (int mt = 0; mt < 4; mt++) {
        #pragma unroll
        for (int nt = 0; nt < 8; nt++) {
            int g0  = btile * BM + wm * 64 + mt * 16 + gid;
            int col = ntile * BN + wn * 64 + nt * 8 + tig * 2;
            size_t r0 = ((size_t)g0 * NODES + n) * ODIM + col;
            size_t r1 = ((size_t)(g0 + 8) * NODES + n) * ODIM + col;
            *reinterpret_cast<float2*>(out + r0) = make_float2(acc[mt][nt][0], acc[mt][nt][1]);
            *reinterpret_cast<float2*>(out + r1) = make_float2(acc[mt][nt][2], acc[mt][nt][3]);
        }
    }
}

extern "C" void kernel_launch(void* const* d_in, const int* in_sizes, int n_in,
                              void* d_out, int out_size) {
    const float* x = (const float*)d_in[0];
    // d_in[1] = batch indices (int64) — implied by layout, unused
    const float* W = (const float*)d_in[2];
    float* out = (float*)d_out;

    pack_w_kernel<<<dim3(FDIM / 32, NODES), 256>>>(W);

    cudaFuncSetAttribute(linear_mlp_node_kernel,
                         cudaFuncAttributeMaxDynamicSharedMemorySize, SMEM_BYTES);
    dim3 grid(NGRAPH / BM, ODIM / BN, NODES);   // (32, 2, 64)
    linear_mlp_node_kernel<<<grid, NTHREADS, SMEM_BYTES>>>(x, out);
}

// round 12
// speedup vs baseline: 1.3340x; 1.3340x over previous
#include <cuda_runtime.h>
#include <cuda_fp16.h>
#include <cstdint>

// out[(b*64+n), :] = x[(b*64+n), :] @ W[n] / 16
// x: [4096*64, 256] f32, W: [64, 256, 256] f32, out: [4096*64, 256] f32
#define NODES   64
#define FDIM    256
#define ODIM    256
#define NGRAPH  4096

#define BM 128          // graphs per CTA
#define BN 128          // output cols per CTA
#define KC 32           // k-chunk
#define NKC (FDIM / KC) // 8
#define NTHREADS 128    // 4 warps, 64x64 warp tiles
#define NSTAGE 3

#define A_ROW_BYTES 80                         // 64B fp16 data + 16B pad (16B-aligned rows, conflict-free ldmatrix)
#define A_STAGE_BYTES (BM * A_ROW_BYTES)       // 10240
#define B_STAGE_BYTES (512 * 16)               // 8192 (512 uint4 = 32k x 128 cols fp16)
#define SMEM_BYTES (NSTAGE * (A_STAGE_BYTES + B_STAGE_BYTES))   // 55296

__device__ __forceinline__ uint32_t smem_u32(const void* p) {
    return (uint32_t)__cvta_generic_to_shared(p);
}
__device__ __forceinline__ void cp_async16(uint32_t s, const void* g) {
    asm volatile("cp.async.cg.shared.global [%0], [%1], 16;" :: "r"(s), "l"(g));
}
__device__ __forceinline__ uint32_t pack_h2(float a, float b) {
    __half2 h = __floats2half2_rn(a, b);
    return *reinterpret_cast<uint32_t*>(&h);
}

// Packed fp16 W fragments for mma.m16n8k16 (B operand, col-major/"row.col"):
// [n][chunk(8)][wn(0..3)][s(0..1)][j(0..3)][lane(0..31)] as uint4:
//   {b0(nt=2j), b1(nt=2j), b0(nt=2j+1), b1(nt=2j+1)} where
//   b0 = fp16x2{W'(k0,o), W'(k0+1,o)}, b1 = fp16x2{W'(k0+8,o), W'(k0+8+1,o)}
//   k0 = chunk*32 + s*16 + 2*tig, o = wn*64 + 16*j + gid (+8 for the second nt)
__device__ uint4 Whp_g[NODES * NKC * 1024];   // 8 MB, L2-resident

__global__ void pack_w_kernel(const float* __restrict__ W) {
    __shared__ float sw[KC * ODIM];     // 32 x 256 = 32KB
    const int n = blockIdx.y;
    const int chunk = blockIdx.x;
    const int tid = threadIdx.x;
    const float4* src = (const float4*)(W + ((size_t)n * FDIM + chunk * KC) * ODIM);
    float4* dst = (float4*)sw;
    #pragma unroll
    for (int i = 0; i < 8; i++)
        dst[tid + i * 256] = src[tid + i * 256];
    __syncthreads();

    const float sc = 0.0625f;   // 1/sqrt(FDIM)
    uint4* outp = Whp_g + ((size_t)n * NKC + chunk) * 1024;
    #pragma unroll
    for (int i = 0; i < 4; i++) {
        int c = tid + i * 256;          // 0..1023
        int lane = c & 31;
        int j    = (c >> 5) & 3;
        int s    = (c >> 7) & 1;
        int wn   = (c >> 8) & 3;
        int gid = lane >> 2, tig = lane & 3;
        int k0 = s * 16 + 2 * tig;
        int o0 = wn * 64 + 16 * j + gid;
        uint4 v;
        v.x = pack_h2(sw[k0 * ODIM + o0] * sc,       sw[(k0 + 1) * ODIM + o0] * sc);
        v.y = pack_h2(sw[(k0 + 8) * ODIM + o0] * sc, sw[(k0 + 9) * ODIM + o0] * sc);
        v.z = pack_h2(sw[k0 * ODIM + o0 + 8] * sc,       sw[(k0 + 1) * ODIM + o0 + 8] * sc);
        v.w = pack_h2(sw[(k0 + 8) * ODIM + o0 + 8] * sc, sw[(k0 + 9) * ODIM + o0 + 8] * sc);
        outp[c] = v;
    }
}

__global__ void __launch_bounds__(NTHREADS, 2)
linear_mlp_node_kernel(const float* __restrict__ x, float* __restrict__ out) {
    extern __shared__ char smem[];
    const uint32_t sA0 = smem_u32(smem);
    char* sBp = smem + NSTAGE * A_STAGE_BYTES;
    const uint32_t sB0 = sA0 + NSTAGE * A_STAGE_BYTES;

    const int tid   = threadIdx.x;
    const int btile = blockIdx.x;   // 0..31
    const int ntile = blockIdx.y;   // 0..1
    const int n     = blockIdx.z;   // 0..63

    const int warp = tid >> 5;      // 0..3
    const int lane = tid & 31;
    const int wm = warp & 1;        // rows wm*64..+63
    const int wn = warp >> 1;       // cols wn*64..+63
    const int gid = lane >> 2;
    const int tig = lane & 3;

    // A load/convert mapping: 8 threads per row, thread covers rows arow+16i
    const int arow = tid >> 3;      // 0..15
    const int acol = tid & 7;       // float4 index within 32-fp32 k-chunk row

    const uint4* WhpN = Whp_g + (size_t)n * NKC * 1024 + (size_t)ntile * 512;

    // ---- A: global fp32 load into regs ----
    auto ldgA = [&](int kc, float4* buf) {
        #pragma unroll
        for (int i = 0; i < 8; i++) {
            const float* g = x + ((size_t)(btile * BM + arow + 16 * i) * NODES + n) * FDIM
                           + kc * KC + acol * 4;
            buf[i] = *reinterpret_cast<const float4*>(g);
        }
    };
    // ---- A: convert + store fp16 to smem stage ----
    auto cvtstsA = [&](int kc, const float4* buf) {
        char* base = smem + (kc % NSTAGE) * A_STAGE_BYTES;
        #pragma unroll
        for (int i = 0; i < 8; i++) {
            uint2 h;
            h.x = pack_h2(buf[i].x, buf[i].y);
            h.y = pack_h2(buf[i].z, buf[i].w);
            *reinterpret_cast<uint2*>(base + (arow + 16 * i) * A_ROW_BYTES + acol * 8) = h;
        }
    };
    // ---- B: cp.async packed fp16 fragments ----
    auto cpB = [&](int kc) {
        uint32_t dst = sB0 + (kc % NSTAGE) * B_STAGE_BYTES;
        const uint4* gB = WhpN + (size_t)kc * 1024;
        #pragma unroll
        for (int i = 0; i < 4; i++) {
            int c = tid + i * NTHREADS;
            cp_async16(dst + c * 16, gB + c);
        }
        asm volatile("cp.async.commit_group;" ::: "memory");
    };

    float acc[4][8][4];
    #pragma unroll
    for (int mt = 0; mt < 4; mt++)
        #pragma unroll
        for (int nt = 0; nt < 8; nt++)
            #pragma unroll
            for (int r = 0; r < 4; r++)
                acc[mt][nt][r] = 0.0f;

    // prologue
    {
        float4 pbuf[8];
        ldgA(0, pbuf); cvtstsA(0, pbuf);
        ldgA(1, pbuf); cvtstsA(1, pbuf);
    }
    cpB(0);
    cpB(1);

    float4 buf[8];
    for (int kc = 0; kc < NKC; kc++) {
        const int stage = kc % NSTAGE;
        if (kc < NKC - 1)
            asm volatile("cp.async.wait_group 1;" ::: "memory");
        else
            asm volatile("cp.async.wait_group 0;" ::: "memory");
        __syncthreads();

        const bool pre = (kc + 2 < NKC);
        if (pre) {
            ldgA(kc + 2, buf);      // latency covered by the MMA section below
            cpB(kc + 2);
        }

        // ldmatrix base for this warp: row = wm*64 + (lane&15), col-half = (lane>>4)*16B
        const uint32_t aBase = sA0 + stage * A_STAGE_BYTES
                             + (wm * 64 + (lane & 15)) * A_ROW_BYTES + (lane >> 4) * 16;
        const uint4* bBase = (const uint4*)(sBp + stage * B_STAGE_BYTES) + wn * 256 + lane;

        #pragma unroll
        for (int s = 0; s < 2; s++) {       // two k16 steps per 32-k chunk
            uint32_t a[4][4];
            uint4 bv[4];
            #pragma unroll
            for (int mt = 0; mt < 4; mt++) {
                asm volatile(
                    "ldmatrix.sync.aligned.m8n8.x4.shared.b16 {%0,%1,%2,%3}, [%4];"
                    : "=r"(a[mt][0]), "=r"(a[mt][1]), "=r"(a[mt][2]), "=r"(a[mt][3])
                    : "r"(aBase + mt * (16 * A_ROW_BYTES) + s * 32));
            }
            #pragma unroll
            for (int j = 0; j < 4; j++)
                bv[j] = bBase[s * 128 + j * 32];

            #pragma unroll
            for (int mt = 0; mt < 4; mt++) {
                #pragma unroll
                for (int j = 0; j < 4; j++) {
                    asm volatile(
                        "mma.sync.aligned.m16n8k16.row.col.f32.f16.f16.f32 "
                        "{%0,%1,%2,%3}, {%4,%5,%6,%7}, {%8,%9}, {%0,%1,%2,%3};"
                        : "+f"(acc[mt][2 * j][0]), "+f"(acc[mt][2 * j][1]),
                          "+f"(acc[mt][2 * j][2]), "+f"(acc[mt][2 * j][3])
                        : "r"(a[mt][0]), "r"(a[mt][1]), "r"(a[mt][2]), "r"(a[mt][3]),
                          "r"(bv[j].x), "r"(bv[j].y));
                    asm volatile(
                        "mma.sync.aligned.m16n8k16.row.col.f32.f16.f16.f32 "
                        "{%0,%1,%2,%3}, {%4,%5,%6,%7}, {%8,%9}, {%0,%1,%2,%3};"
                        : "+f"(acc[mt][2 * j + 1][0]), "+f"(acc[mt][2 * j + 1][1]),
                          "+f"(acc[mt][2 * j + 1][2]), "+f"(acc[mt][2 * j + 1][3])
                        : "r"(a[mt][0]), "r"(a[mt][1]), "r"(a[mt][2]), "r"(a[mt][3]),
                          "r"(bv[j].z), "r"(bv[j].w));
                }
            }
        }

        if (pre)
            cvtstsA(kc + 2, buf);   // writes stage read last at iter kc-1; barrier-protected
    }

    // epilogue (scale folded into W)
    #pragma unroll
    for (int mt = 0; mt < 4; mt++) {
        #pragma unroll
        for (int nt = 0; nt < 8; nt++) {
            int g0  = btile * BM + wm * 64 + mt * 16 + gid;
            int col = ntile * BN + wn * 64 + nt * 8 + tig * 2;
            size_t r0 = ((size_t)g0 * NODES + n) * ODIM + col;
            size_t r1 = ((size_t)(g0 + 8) * NODES + n) * ODIM + col;
            *reinterpret_cast<float2*>(out + r0) = make_float2(acc[mt][nt][0], acc[mt][nt][1]);
            *reinterpret_cast<float2*>(out + r1) = make_float2(acc[mt][nt][2], acc[mt][nt][3]);
        }
    }
}

extern "C" void kernel_launch(void* const* d_in, const int* in_sizes, int n_in,
                              void* d_out, int out_size) {
    const float* x = (const float*)d_in[0];
    // d_in[1] = batch indices (int64) — implied by layout, unused
    const float* W = (const float*)d_in[2];
    float* out = (float*)d_out;

    pack_w_kernel<<<dim3(NKC, NODES), 256>>>(W);

    cudaFuncSetAttribute(linear_mlp_node_kernel,
                         cudaFuncAttributeMaxDynamicSharedMemorySize, SMEM_BYTES);
    dim3 grid(NGRAPH / BM, ODIM / BN, NODES);   // (32, 2, 64)
    linear_mlp_node_kernel<<<grid, NTHREADS, SMEM_BYTES>>>(x, out);
}